// round 11
// baseline (speedup 1.0000x reference)
#include <cuda_runtime.h>
#include <cstdint>

// ---------------------------------------------------------------------------
// y = W8(...(W0 x + b0)...) + b8  ->  y = W_eff x + b_eff,  W_eff [10,784].
// R11: gemv = 8 kg-lanes x 4 rg x 4 rows/lane: W-LDS wavefronts amortized over
//      16 rows (3.5 wf/row-chunk vs 6) -> L1tex drops below the DRAM roof.
//      Scalar FFMA accs (B300 fma pipe has 2x headroom), launch_bounds(256,3).
// ---------------------------------------------------------------------------

#define K_IN   784
#define N_OUT  10

__device__ float g_Weff[N_OUT * K_IN];
__device__ float g_beff[N_OUT];

// ---------------------------------------------------------------------------
// fold_fused: 7 CTAs x 768 threads (unchanged from R10).
// ---------------------------------------------------------------------------
template<int N, int M>
__device__ __forceinline__ void fold_step(float* A, float* T, float* beff,
    const float* W, const float* b, int t)
{
    if (t < N_OUT) {
        float s = 0.f;
#pragma unroll
        for (int k = 0; k < N; ++k) s += A[t * N + k] * b[k];
        beff[t] += s;
    }
    for (int idx = t; idx < N_OUT * M; idx += 768) {
        int r = idx / M, c = idx - r * M;
        float s = 0.f;
#pragma unroll
        for (int k = 0; k < N; ++k) s += A[r * N + k] * W[k * M + c];
        T[idx] = s;
    }
    __syncthreads();
    for (int idx = t; idx < N_OUT * M; idx += 768) A[idx] = T[idx];
    __syncthreads();
}

__global__ __launch_bounds__(768) void fold_fused(
    const float* __restrict__ W0, const float* __restrict__ b0,
    const float* __restrict__ W1, const float* __restrict__ b1,
    const float* __restrict__ W2, const float* __restrict__ b2,
    const float* __restrict__ W3, const float* __restrict__ b3,
    const float* __restrict__ W4, const float* __restrict__ b4,
    const float* __restrict__ W5, const float* __restrict__ b5,
    const float* __restrict__ W6, const float* __restrict__ b6,
    const float* __restrict__ W7, const float* __restrict__ b7,
    const float* __restrict__ W8, const float* __restrict__ b8)
{
    __shared__ float A[10 * 69], T[10 * 69], beff[N_OUT];
    __shared__ float sw[3049];
    __shared__ float sbv[170];

    const int t = threadIdx.x;

    float* sW1 = sw;          float* sW2 = sw + 2139;
    float* sW3 = sw + 2449;   float* sW4 = sw + 2549;
    float* sW5 = sw + 2649;   float* sW6 = sw + 2749;
    float* sW7 = sw + 2849;   float* sW8 = sw + 2949;
    float* sb0 = sbv;         float* sb1 = sbv + 69;
    float* sb2 = sbv + 100;   float* sb3 = sbv + 110;
    float* sb4 = sbv + 120;   float* sb5 = sbv + 130;
    float* sb6 = sbv + 140;   float* sb7 = sbv + 150;
    float* sb8 = sbv + 160;

    for (int i = t; i < 2139; i += 768) sW1[i] = W1[i];
    if (t < 310) sW2[t] = W2[t];
    if (t < 100) { sW3[t] = W3[t]; sW4[t] = W4[t]; sW5[t] = W5[t];
                   sW6[t] = W6[t]; sW7[t] = W7[t]; sW8[t] = W8[t]; }
    if (t < 69) sb0[t] = b0[t];
    if (t < 31) sb1[t] = b1[t];
    if (t < 10) { sb2[t] = b2[t]; sb3[t] = b3[t]; sb4[t] = b4[t];
                  sb5[t] = b5[t]; sb6[t] = b6[t]; sb7[t] = b7[t];
                  sb8[t] = b8[t]; }
    __syncthreads();

    if (t < 100) A[t] = sW8[t];
    if (t < N_OUT) beff[t] = sb8[t];
    __syncthreads();

    fold_step<10, 10>(A, T, beff, sW7, sb7, t);
    fold_step<10, 10>(A, T, beff, sW6, sb6, t);
    fold_step<10, 10>(A, T, beff, sW5, sb5, t);
    fold_step<10, 10>(A, T, beff, sW4, sb4, t);
    fold_step<10, 10>(A, T, beff, sW3, sb3, t);
    fold_step<10, 31>(A, T, beff, sW2, sb2, t);
    fold_step<31, 69>(A, T, beff, sW1, sb1, t);   // A now [10,69]

    if (blockIdx.x == 0 && t < N_OUT) {
        float s = 0.f;
#pragma unroll
        for (int k = 0; k < 69; ++k) s += A[t * 69 + k] * sb0[k];
        g_beff[t] = beff[t] + s;
    }

    if (t < 112) {
        const int col = blockIdx.x * 112 + t;
        float acc[N_OUT];
#pragma unroll
        for (int r = 0; r < N_OUT; ++r) acc[r] = 0.f;
#pragma unroll
        for (int k = 0; k < 69; ++k) {
            float w0 = W0[k * K_IN + col];
#pragma unroll
            for (int r = 0; r < N_OUT; ++r) acc[r] += A[r * 69 + k] * w0;
        }
#pragma unroll
        for (int r = 0; r < N_OUT; ++r) g_Weff[r * K_IN + col] = acc[r];
    }
}

// ---------------------------------------------------------------------------
// gemv_direct: grid = B/128 CTAs x 256 threads (8 warps x 16 rows = 128 rows).
// warp = 8 kg-lanes x 4 rg-groups, 4 rows/lane.
// Per 32-col iter: 4 LDG.128 (pipelined), 10 LDS.128 (conflict-free 4-way
// bcast, amortized over 16 rows), 160 scalar FFMA.
// ---------------------------------------------------------------------------
#define ROWS_PL 4   // rows per lane

__global__ __launch_bounds__(256, 3) void gemv_direct(
    const float* __restrict__ x, float* __restrict__ y, int B)
{
    __shared__ float sW[N_OUT * K_IN + 16];   // +16 pad for tail W reads
    __shared__ float sb[N_OUT];

    const int tid = threadIdx.x;

    for (int i = tid; i < N_OUT * K_IN; i += 256) sW[i] = g_Weff[i];
    if (tid < 16) sW[N_OUT * K_IN + tid] = 0.f;
    if (tid < N_OUT) sb[tid] = g_beff[tid];
    __syncthreads();

    const int lane = tid & 31;
    const int warp = tid >> 5;
    const int kg = lane & 7;            // column lane 0..7 (16B granule)
    const int rg = lane >> 3;           // row group 0..3
    const int row0 = blockIdx.x * 128 + warp * 16 + rg * ROWS_PL;

    // clamped per-row pointers (loads always legal; stores predicated)
    const float* p[ROWS_PL];
#pragma unroll
    for (int r = 0; r < ROWS_PL; ++r) {
        int rr = row0 + r;
        p[r] = x + (size_t)(rr < B ? rr : 0) * K_IN + 4 * kg;
    }

    float acc[N_OUT][ROWS_PL];
#pragma unroll
    for (int j = 0; j < N_OUT; ++j)
#pragma unroll
        for (int r = 0; r < ROWS_PL; ++r) acc[j][r] = 0.f;

    float4 xc[ROWS_PL];
#pragma unroll
    for (int r = 0; r < ROWS_PL; ++r)
        xc[r] = *reinterpret_cast<const float4*>(p[r]);

#pragma unroll 1
    for (int i = 0; i < 25; ++i) {
        const int c = 4 * kg + 32 * i;

        // prefetch next iteration (iter 24 = 16-col tail: only kg<4 has data)
        float4 xn[ROWS_PL];
#pragma unroll
        for (int r = 0; r < ROWS_PL; ++r) {
            xn[r].x = xn[r].y = xn[r].z = xn[r].w = 0.f;
        }
        if (i < 23) {
#pragma unroll
            for (int r = 0; r < ROWS_PL; ++r)
                xn[r] = *reinterpret_cast<const float4*>(p[r] + 32 * (i + 1));
        } else if (i == 23 && kg < 4) {
#pragma unroll
            for (int r = 0; r < ROWS_PL; ++r)
                xn[r] = *reinterpret_cast<const float4*>(p[r] + 768);
        }

#pragma unroll
        for (int j = 0; j < N_OUT; ++j) {
            float4 w = *reinterpret_cast<const float4*>(&sW[j * K_IN + c]);
#pragma unroll
            for (int r = 0; r < ROWS_PL; ++r) {
                acc[j][r] += xc[r].x * w.x;
                acc[j][r] += xc[r].y * w.y;
                acc[j][r] += xc[r].z * w.z;
                acc[j][r] += xc[r].w * w.w;
            }
        }
#pragma unroll
        for (int r = 0; r < ROWS_PL; ++r) xc[r] = xn[r];
    }

    // butterfly reduce over the 8 kg lanes
#pragma unroll
    for (int m = 1; m <= 4; m <<= 1)
#pragma unroll
        for (int j = 0; j < N_OUT; ++j)
#pragma unroll
            for (int r = 0; r < ROWS_PL; ++r)
                acc[j][r] += __shfl_xor_sync(0xFFFFFFFFu, acc[j][r], m);

    // lanes kg=0..4 write float2 pair #kg for their 4 rows
    if (kg < 5) {
#pragma unroll
        for (int r = 0; r < ROWS_PL; ++r) {
            const int row = row0 + r;
            if (row < B) {
                float2 v;
                v.x = acc[2 * kg][r]     + sb[2 * kg];
                v.y = acc[2 * kg + 1][r] + sb[2 * kg + 1];
                *reinterpret_cast<float2*>(y + (size_t)row * N_OUT + 2 * kg) = v;
            }
        }
    }
}

// ---------------------------------------------------------------------------
extern "C" void kernel_launch(void* const* d_in, const int* in_sizes, int n_in,
                              void* d_out, int out_size)
{
    const float* x = (const float*)d_in[0];
    const float* W[9];
    const float* b[9];
    for (int i = 0; i < 9; ++i) {
        W[i] = (const float*)d_in[1 + 2 * i];
        b[i] = (const float*)d_in[2 + 2 * i];
    }
    const int B = in_sizes[0] / K_IN;

    fold_fused<<<7, 768>>>(W[0], b[0], W[1], b[1], W[2], b[2], W[3], b[3],
                           W[4], b[4], W[5], b[5], W[6], b[6], W[7], b[7],
                           W[8], b[8]);

    float* y = (float*)d_out;
    gemv_direct<<<(B + 127) / 128, 256>>>(x, y, B);
}

// round 12
// speedup vs baseline: 1.0862x; 1.0862x over previous
#include <cuda_runtime.h>
#include <cstdint>

// ---------------------------------------------------------------------------
// y = W8(...(W0 x + b0)...) + b8  ->  y = W_eff x + b_eff,  W_eff [10,784].
// R12: gemv = 8 kg x 4 rg x 4 rows/lane (16 rows/warp W-amortization, R11)
//      at 64 regs / 4 CTAs / 32 warps (R10's occupancy): no prefetch buffers,
//      single base pointer + immediate row offsets, group-clamped tail.
//      grid 512 <= 592 capacity -> single wave, no tail.
// ---------------------------------------------------------------------------

#define K_IN   784
#define N_OUT  10

__device__ float g_Weff[N_OUT * K_IN];
__device__ float g_beff[N_OUT];

// ---------------------------------------------------------------------------
// fold_fused: 7 CTAs x 768 threads (unchanged, known-correct).
// ---------------------------------------------------------------------------
template<int N, int M>
__device__ __forceinline__ void fold_step(float* A, float* T, float* beff,
    const float* W, const float* b, int t)
{
    if (t < N_OUT) {
        float s = 0.f;
#pragma unroll
        for (int k = 0; k < N; ++k) s += A[t * N + k] * b[k];
        beff[t] += s;
    }
    for (int idx = t; idx < N_OUT * M; idx += 768) {
        int r = idx / M, c = idx - r * M;
        float s = 0.f;
#pragma unroll
        for (int k = 0; k < N; ++k) s += A[r * N + k] * W[k * M + c];
        T[idx] = s;
    }
    __syncthreads();
    for (int idx = t; idx < N_OUT * M; idx += 768) A[idx] = T[idx];
    __syncthreads();
}

__global__ __launch_bounds__(768) void fold_fused(
    const float* __restrict__ W0, const float* __restrict__ b0,
    const float* __restrict__ W1, const float* __restrict__ b1,
    const float* __restrict__ W2, const float* __restrict__ b2,
    const float* __restrict__ W3, const float* __restrict__ b3,
    const float* __restrict__ W4, const float* __restrict__ b4,
    const float* __restrict__ W5, const float* __restrict__ b5,
    const float* __restrict__ W6, const float* __restrict__ b6,
    const float* __restrict__ W7, const float* __restrict__ b7,
    const float* __restrict__ W8, const float* __restrict__ b8)
{
    __shared__ float A[10 * 69], T[10 * 69], beff[N_OUT];
    __shared__ float sw[3049];
    __shared__ float sbv[170];

    const int t = threadIdx.x;

    float* sW1 = sw;          float* sW2 = sw + 2139;
    float* sW3 = sw + 2449;   float* sW4 = sw + 2549;
    float* sW5 = sw + 2649;   float* sW6 = sw + 2749;
    float* sW7 = sw + 2849;   float* sW8 = sw + 2949;
    float* sb0 = sbv;         float* sb1 = sbv + 69;
    float* sb2 = sbv + 100;   float* sb3 = sbv + 110;
    float* sb4 = sbv + 120;   float* sb5 = sbv + 130;
    float* sb6 = sbv + 140;   float* sb7 = sbv + 150;
    float* sb8 = sbv + 160;

    for (int i = t; i < 2139; i += 768) sW1[i] = W1[i];
    if (t < 310) sW2[t] = W2[t];
    if (t < 100) { sW3[t] = W3[t]; sW4[t] = W4[t]; sW5[t] = W5[t];
                   sW6[t] = W6[t]; sW7[t] = W7[t]; sW8[t] = W8[t]; }
    if (t < 69) sb0[t] = b0[t];
    if (t < 31) sb1[t] = b1[t];
    if (t < 10) { sb2[t] = b2[t]; sb3[t] = b3[t]; sb4[t] = b4[t];
                  sb5[t] = b5[t]; sb6[t] = b6[t]; sb7[t] = b7[t];
                  sb8[t] = b8[t]; }
    __syncthreads();

    if (t < 100) A[t] = sW8[t];
    if (t < N_OUT) beff[t] = sb8[t];
    __syncthreads();

    fold_step<10, 10>(A, T, beff, sW7, sb7, t);
    fold_step<10, 10>(A, T, beff, sW6, sb6, t);
    fold_step<10, 10>(A, T, beff, sW5, sb5, t);
    fold_step<10, 10>(A, T, beff, sW4, sb4, t);
    fold_step<10, 10>(A, T, beff, sW3, sb3, t);
    fold_step<10, 31>(A, T, beff, sW2, sb2, t);
    fold_step<31, 69>(A, T, beff, sW1, sb1, t);   // A now [10,69]

    if (blockIdx.x == 0 && t < N_OUT) {
        float s = 0.f;
#pragma unroll
        for (int k = 0; k < 69; ++k) s += A[t * 69 + k] * sb0[k];
        g_beff[t] = beff[t] + s;
    }

    if (t < 112) {
        const int col = blockIdx.x * 112 + t;
        float acc[N_OUT];
#pragma unroll
        for (int r = 0; r < N_OUT; ++r) acc[r] = 0.f;
#pragma unroll
        for (int k = 0; k < 69; ++k) {
            float w0 = W0[k * K_IN + col];
#pragma unroll
            for (int r = 0; r < N_OUT; ++r) acc[r] += A[r * 69 + k] * w0;
        }
#pragma unroll
        for (int r = 0; r < N_OUT; ++r) g_Weff[r * K_IN + col] = acc[r];
    }
}

// ---------------------------------------------------------------------------
// gemv_direct: grid = B/128 CTAs x 256 threads (8 warps x 16 rows = 128 rows).
// warp = 8 kg-lanes x 4 rg-groups, 4 rows/lane (contiguous -> one base ptr,
// immediate offsets r*K_IN). No prefetch buffers: 32 warps/SM hide latency.
// Per 32-col iter: 4 LDG.128, 10 LDS.128 (conflict-free 4-way bcast,
// amortized over 16 rows), 160 scalar FFMA.
// ---------------------------------------------------------------------------
#define ROWS_PL 4

__global__ __launch_bounds__(256, 4) void gemv_direct(
    const float* __restrict__ x, float* __restrict__ y, int B)
{
    __shared__ float sW[N_OUT * K_IN + 16];   // +16 pad: tail W reads safe
    __shared__ float sb[N_OUT];

    const int tid = threadIdx.x;

    for (int i = tid; i < N_OUT * K_IN; i += 256) sW[i] = g_Weff[i];
    if (tid < 16) sW[N_OUT * K_IN + tid] = 0.f;
    if (tid < N_OUT) sb[tid] = g_beff[tid];
    __syncthreads();

    const int lane = tid & 31;
    const int warp = tid >> 5;
    const int kg = lane & 7;            // column lane 0..7 (16B granule)
    const int rg = lane >> 3;           // row group 0..3
    int row0 = blockIdx.x * 128 + warp * 16 + rg * ROWS_PL;
    // group clamp: keep the 4-row window in-bounds; overlapping groups
    // produce duplicate stores of IDENTICAL values (benign).
    if (row0 > B - ROWS_PL) row0 = (B >= ROWS_PL) ? (B - ROWS_PL) : 0;

    const float* xb = x + (size_t)row0 * K_IN + 4 * kg;

    float acc[N_OUT][ROWS_PL];
#pragma unroll
    for (int j = 0; j < N_OUT; ++j)
#pragma unroll
        for (int r = 0; r < ROWS_PL; ++r) acc[j][r] = 0.f;

#pragma unroll 1
    for (int i = 0; i < 25; ++i) {
        const int c = 4 * kg + 32 * i;
        const bool ld = (i < 24) | (kg < 4);   // iter 24 = 16-col tail

        float4 xv[ROWS_PL];
#pragma unroll
        for (int r = 0; r < ROWS_PL; ++r) {
            if (ld) {
                xv[r] = *reinterpret_cast<const float4*>(
                    xb + (size_t)r * K_IN + 32 * i);
            } else {
                xv[r].x = xv[r].y = xv[r].z = xv[r].w = 0.f;
            }
        }

#pragma unroll
        for (int j = 0; j < N_OUT; ++j) {
            // tail: kg>=4 -> c up to 796; sW pad covers j=9 overrun; other js
            // read neighbor-row values but multiply by x==0 -> harmless.
            float4 w = *reinterpret_cast<const float4*>(&sW[j * K_IN + c]);
#pragma unroll
            for (int r = 0; r < ROWS_PL; ++r) {
                acc[j][r] += xv[r].x * w.x;
                acc[j][r] += xv[r].y * w.y;
                acc[j][r] += xv[r].z * w.z;
                acc[j][r] += xv[r].w * w.w;
            }
        }
    }

    // butterfly reduce over the 8 kg lanes
#pragma unroll
    for (int m = 1; m <= 4; m <<= 1)
#pragma unroll
        for (int j = 0; j < N_OUT; ++j)
#pragma unroll
            for (int r = 0; r < ROWS_PL; ++r)
                acc[j][r] += __shfl_xor_sync(0xFFFFFFFFu, acc[j][r], m);

    // lanes kg=0..4 write float2 pair #kg for their 4 rows
    if (kg < 5) {
#pragma unroll
        for (int r = 0; r < ROWS_PL; ++r) {
            const int row = row0 + r;
            if (row < B) {
                float2 v;
                v.x = acc[2 * kg][r]     + sb[2 * kg];
                v.y = acc[2 * kg + 1][r] + sb[2 * kg + 1];
                *reinterpret_cast<float2*>(y + (size_t)row * N_OUT + 2 * kg) = v;
            }
        }
    }
}

// ---------------------------------------------------------------------------
extern "C" void kernel_launch(void* const* d_in, const int* in_sizes, int n_in,
                              void* d_out, int out_size)
{
    const float* x = (const float*)d_in[0];
    const float* W[9];
    const float* b[9];
    for (int i = 0; i < 9; ++i) {
        W[i] = (const float*)d_in[1 + 2 * i];
        b[i] = (const float*)d_in[2 + 2 * i];
    }
    const int B = in_sizes[0] / K_IN;

    fold_fused<<<7, 768>>>(W[0], b[0], W[1], b[1], W[2], b[2], W[3], b[3],
                           W[4], b[4], W[5], b[5], W[6], b[6], W[7], b[7],
                           W[8], b[8]);

    float* y = (float*)d_out;
    gemv_direct<<<(B + 127) / 128, 256>>>(x, y, B);
}